// round 5
// baseline (speedup 1.0000x reference)
#include <cuda_runtime.h>

#define BB 8
#define N_IN 20000
#define NPAD 20480
#define N_ALL 1200
#define NPT 1024
#define KNB 34
#define CC 96
#define HH 6
#define NROWS (BB*NPT)

// ---------------- scratch (device globals; no allocation allowed) ----------------
__device__ float d_xs[BB*NPAD];
__device__ float d_ys[BB*NPAD];
__device__ float d_zs[BB*NPAD];
__device__ int   d_fps[BB*N_ALL];
__device__ float d_coord[NROWS*3];
__device__ float d_color[NROWS*3];
__device__ int   d_nidx[NROWS*KNB];
__device__ int   d_ncnt[NROWS];
__device__ float d_x [NROWS*CC];
__device__ float d_qb[NROWS*CC];
__device__ float d_kb[NROWS*CC];
__device__ float d_vb[NROWS*CC];
__device__ float d_ao[NROWS*CC];
__device__ float d_x1[NROWS*CC];

// ---------------- 0: SoA transpose of point clouds (pad with point 0 clone) -------
__global__ void k_transpose(const float* __restrict__ pc) {
    int idx = blockIdx.x*blockDim.x + threadIdx.x;
    if (idx >= BB*NPAD) return;
    int b = idx / NPAD, i = idx - b*NPAD;
    int src = (i < N_IN) ? i : 0;                 // pad = clone of point 0 (dist->0, never argmax)
    const float* p = pc + ((long)b*N_IN + src)*3;
    d_xs[idx] = p[0]; d_ys[idx] = p[1]; d_zs[idx] = p[2];
}

// ---------------- 1: farthest point sampling, 1 block per batch -------------------
__global__ __launch_bounds__(512, 1) void k_fps() {
    const int b = blockIdx.x, tid = threadIdx.x;
    const int lane = tid & 31, wid = tid >> 5;
    const float4* X4 = (const float4*)(d_xs + b*NPAD);
    const float4* Y4 = (const float4*)(d_ys + b*NPAD);
    const float4* Z4 = (const float4*)(d_zs + b*NPAD);
    const float* Xs = d_xs + b*NPAD;
    const float* Ys = d_ys + b*NPAD;
    const float* Zs = d_zs + b*NPAD;

    float dist[40];
#pragma unroll
    for (int i = 0; i < 40; ++i) dist[i] = 1e10f;

    __shared__ float s_v[16];
    __shared__ int   s_i[16];
    __shared__ int   s_cur;

    int cur = 0;
    for (int t = 0; t < N_ALL; ++t) {
        if (tid == 0) d_fps[b*N_ALL + t] = cur;
        float cx = __ldg(Xs + cur), cy = __ldg(Ys + cur), cz = __ldg(Zs + cur);
        float best = -1.0f; int bidx = 0;
#pragma unroll
        for (int k = 0; k < 10; ++k) {
            int f4 = k*512 + tid;                 // block-strided: warp reads contiguous 512B
            float4 px = X4[f4], py = Y4[f4], pz = Z4[f4];
#pragma unroll
            for (int m = 0; m < 4; ++m) {
                float x = (m==0)?px.x:(m==1)?px.y:(m==2)?px.z:px.w;
                float y = (m==0)?py.x:(m==1)?py.y:(m==2)?py.z:py.w;
                float z = (m==0)?pz.x:(m==1)?pz.y:(m==2)?pz.z:pz.w;
                float dx = __fadd_rn(x, -cx);
                float dy = __fadd_rn(y, -cy);
                float dz = __fadd_rn(z, -cz);
                // match XLA: mul then summed adds, no fma contraction
                float d = __fadd_rn(__fadd_rn(__fmul_rn(dx,dx), __fmul_rn(dy,dy)), __fmul_rn(dz,dz));
                int idx = k*40; // placeholder, recomputed below
                (void)idx;
                float nd = fminf(dist[k*4+m], d);
                dist[k*4+m] = nd;
                int j = f4*4 + m;
                if (nd > best) { best = nd; bidx = j; }   // strict > : first occurrence wins
            }
        }
        // warp argmax reduce (tie -> lower index)
#pragma unroll
        for (int off = 16; off > 0; off >>= 1) {
            float ov = __shfl_down_sync(0xffffffffu, best, off);
            int   oi = __shfl_down_sync(0xffffffffu, bidx, off);
            if (ov > best || (ov == best && oi < bidx)) { best = ov; bidx = oi; }
        }
        if (lane == 0) { s_v[wid] = best; s_i[wid] = bidx; }
        __syncthreads();
        if (tid == 0) {
            float bv = s_v[0]; int bi = s_i[0];
#pragma unroll
            for (int w = 1; w < 16; ++w) {
                float ov = s_v[w]; int oi = s_i[w];
                if (ov > bv || (ov == bv && oi < bi)) { bv = ov; bi = oi; }
            }
            s_cur = bi;
        }
        __syncthreads();
        cur = s_cur;
    }
}

// ---------------- 2: gather selected points (fps_idx[:, sel]) --------------------
__global__ void k_gather(const float* __restrict__ pc, const float* __restrict__ col,
                         const int* __restrict__ sel, float* __restrict__ out_coord) {
    int p = blockIdx.x*blockDim.x + threadIdx.x;
    if (p >= NROWS) return;
    int b = p >> 10, i = p & 1023;
    int gi = d_fps[b*N_ALL + sel[i]];
    const float* s  = pc  + ((long)b*N_IN + gi)*3;
    const float* s2 = col + ((long)b*N_IN + gi)*3;
    d_coord[p*3+0] = s[0];  d_coord[p*3+1] = s[1];  d_coord[p*3+2] = s[2];
    d_color[p*3+0] = s2[0]; d_color[p*3+1] = s2[1]; d_color[p*3+2] = s2[2];
    out_coord[p*3+0] = s[0]; out_coord[p*3+1] = s[1]; out_coord[p*3+2] = s[2];
}

// ---------------- 3: radius neighbors, one warp per query point ------------------
__global__ __launch_bounds__(256) void k_neighbor() {
    __shared__ float sx[NPT], sy[NPT], sz[NPT];
    const int b = blockIdx.y;
    for (int i = threadIdx.x; i < NPT; i += 256) {
        const float* cp = d_coord + (b*NPT + i)*3;
        sx[i] = cp[0]; sy[i] = cp[1]; sz[i] = cp[2];
    }
    __syncthreads();
    const int warp = threadIdx.x >> 5, lane = threadIdx.x & 31;
    const int pl = blockIdx.x*8 + warp;
    const int p  = b*NPT + pl;
    const float qx = sx[pl], qy = sy[pl], qz = sz[pl];
    const float R2 = 0.010000000000000002f;
    float key[32];
    int nv = 0;
#pragma unroll
    for (int i = 0; i < 32; ++i) {
        int c = i*32 + lane;
        float dx = __fadd_rn(qx, -sx[c]);
        float dy = __fadd_rn(qy, -sy[c]);
        float dz = __fadd_rn(qz, -sz[c]);
        float d2 = __fadd_rn(__fadd_rn(__fmul_rn(dx,dx), __fmul_rn(dy,dy)), __fmul_rn(dz,dz));
        bool v = (d2 <= R2);
        key[i] = v ? d2 : 1e10f;
        nv += v ? 1 : 0;
    }
    int total = nv;
#pragma unroll
    for (int off = 16; off > 0; off >>= 1) total += __shfl_xor_sync(0xffffffffu, total, off);

    int* my = d_nidx + p*KNB;
    if (total <= KNB) {
        int pos = 0;
#pragma unroll
        for (int i = 0; i < 32; ++i) {
            bool v = key[i] < 1e9f;
            unsigned m = __ballot_sync(0xffffffffu, v);
            if (v) my[pos + __popc(m & ((1u<<lane)-1u))] = i*32 + lane;
            pos += __popc(m);
        }
        for (int s = pos + lane; s < KNB; s += 32) my[s] = pl;  // padded slots: self
        if (lane == 0) d_ncnt[p] = total;
    } else {
        for (int s = 0; s < KNB; ++s) {
            float bv = 3e10f; int bi = 0x7fffffff;
#pragma unroll
            for (int i = 0; i < 32; ++i) {
                int c = i*32 + lane;
                if (key[i] < bv || (key[i] == bv && c < bi)) { bv = key[i]; bi = c; }
            }
#pragma unroll
            for (int off = 16; off > 0; off >>= 1) {
                float ov = __shfl_xor_sync(0xffffffffu, bv, off);
                int   oi = __shfl_xor_sync(0xffffffffu, bi, off);
                if (ov < bv || (ov == bv && oi < bi)) { bv = ov; bi = oi; }
            }
            if ((bi & 31) == lane) {
#pragma unroll
                for (int i = 0; i < 32; ++i) if (i*32 + lane == bi) key[i] = 2e10f;
            }
            if (lane == 0) my[s] = bi;
        }
        if (lane == 0) d_ncnt[p] = KNB;
    }
}

// ---------------- 4: x = feat@W_in+b ; q,k,v projections -------------------------
__global__ __launch_bounds__(96) void k_inproj(const float* __restrict__ Wi, const float* __restrict__ bi,
                                               const float* __restrict__ Wq, const float* __restrict__ Wk,
                                               const float* __restrict__ Wv) {
    __shared__ float sf[16][6];
    __shared__ float sx[16][96];
    const int t = threadIdx.x, r0 = blockIdx.x*16;
    {
        int r = t/6, j = t - r*6, row = r0 + r;
        sf[r][j] = (j < 3) ? d_color[row*3 + j] : d_coord[row*3 + j - 3];
    }
    __syncthreads();
    const int c = t;
    const float bc = bi[c];
#pragma unroll
    for (int r = 0; r < 16; ++r) {
        float a = bc;
#pragma unroll
        for (int j = 0; j < 6; ++j) a = __fmaf_rn(sf[r][j], Wi[j*96 + c], a);
        sx[r][c] = a;
        d_x[(r0 + r)*96 + c] = a;
    }
    __syncthreads();
    float aq[16], ak[16], av[16];
#pragma unroll
    for (int r = 0; r < 16; ++r) { aq[r] = 0.f; ak[r] = 0.f; av[r] = 0.f; }
    for (int j = 0; j < 96; ++j) {
        float wq = Wq[j*96 + c], wk = Wk[j*96 + c], wv = Wv[j*96 + c];
#pragma unroll
        for (int r = 0; r < 16; ++r) {
            float xv = sx[r][j];
            aq[r] = __fmaf_rn(xv, wq, aq[r]);
            ak[r] = __fmaf_rn(xv, wk, ak[r]);
            av[r] = __fmaf_rn(xv, wv, av[r]);
        }
    }
#pragma unroll
    for (int r = 0; r < 16; ++r) {
        d_qb[(r0 + r)*96 + c] = aq[r];
        d_kb[(r0 + r)*96 + c] = ak[r];
        d_vb[(r0 + r)*96 + c] = av[r];
    }
}

// ---------------- 5: local attention, one block per point ------------------------
__global__ __launch_bounds__(192) void k_attn(const float* __restrict__ Wpos) {
    const int p = blockIdx.x, pl = p & 1023, base = p - pl;
    const int t = threadIdx.x;
    __shared__ float sq[96];
    __shared__ float skn[KNB][96];
    __shared__ float svn[KNB][96];
    __shared__ float sdx[KNB], sdy[KNB], sdz[KNB];
    __shared__ int   snb[KNB];
    __shared__ float slog[HH*KNB];
    __shared__ int   scnt;

    if (t < KNB) {
        int nb = d_nidx[p*KNB + t];
        snb[t] = nb;
        int gn = base + nb;
        sdx[t] = __fadd_rn(d_coord[p*3+0], -d_coord[gn*3+0]);
        sdy[t] = __fadd_rn(d_coord[p*3+1], -d_coord[gn*3+1]);
        sdz[t] = __fadd_rn(d_coord[p*3+2], -d_coord[gn*3+2]);
    }
    if (t < 96) sq[t] = d_qb[p*96 + t];
    if (t == 0) scnt = d_ncnt[p];
    __syncthreads();

    for (int e = t; e < KNB*96; e += 192) {
        int kk = e / 96, c = e - kk*96;
        int gn = base + snb[kk];
        float pe = __fmaf_rn(sdz[kk], Wpos[192 + c],
                   __fmaf_rn(sdy[kk], Wpos[96 + c],
                   __fmul_rn(sdx[kk], Wpos[c])));
        skn[kk][c] = __fadd_rn(d_kb[gn*96 + c], pe);
        svn[kk][c] = __fadd_rn(d_vb[gn*96 + c], pe);
    }
    __syncthreads();

    const int cnt = scnt;
    for (int e = t; e < HH*KNB; e += 192) {
        int h = e / KNB, kk = e - h*KNB;
        float a = 0.f;
#pragma unroll
        for (int d = 0; d < 16; ++d) a = __fmaf_rn(sq[h*16 + d], skn[kk][h*16 + d], a);
        slog[h*KNB + kk] = (kk < cnt) ? __fmul_rn(a, 0.25f) : -1e9f;
    }
    __syncthreads();

    { // softmax: warp w == head w (6 warps exactly)
        int w = t >> 5, lane = t & 31;
        float v0 = slog[w*KNB + lane];
        float v1 = (lane < 2) ? slog[w*KNB + 32 + lane] : -3.0e38f;
        float m = fmaxf(v0, v1);
#pragma unroll
        for (int off = 16; off > 0; off >>= 1) m = fmaxf(m, __shfl_xor_sync(0xffffffffu, m, off));
        float e0 = expf(v0 - m);
        float e1 = (lane < 2) ? expf(v1 - m) : 0.f;
        float s = e0 + e1;
#pragma unroll
        for (int off = 16; off > 0; off >>= 1) s += __shfl_xor_sync(0xffffffffu, s, off);
        float inv = 1.0f / s;
        slog[w*KNB + lane] = e0 * inv;
        if (lane < 2) slog[w*KNB + 32 + lane] = e1 * inv;
    }
    __syncthreads();

    if (t < 96) {
        int h = t >> 4;
        float a = 0.f;
#pragma unroll
        for (int kk = 0; kk < KNB; ++kk) a = __fmaf_rn(slog[h*KNB + kk], svn[kk][t], a);
        d_ao[p*96 + t] = a;
    }
}

// ---------------- 6: x1 = LN(x + ao@Wo), one warp per row ------------------------
__global__ __launch_bounds__(256) void k_wo_ln(const float* __restrict__ Wo, const float* __restrict__ g1,
                                               const float* __restrict__ be1) {
    __shared__ float srow[8][96];
    const int w = threadIdx.x >> 5, lane = threadIdx.x & 31;
    const int r = blockIdx.x*8 + w;
    const int c0 = lane, c1 = lane + 32, c2 = lane + 64;
    srow[w][c0] = d_ao[r*96 + c0];
    srow[w][c1] = d_ao[r*96 + c1];
    srow[w][c2] = d_ao[r*96 + c2];
    float x0 = d_x[r*96 + c0], x1v = d_x[r*96 + c1], x2v = d_x[r*96 + c2];
    __syncwarp();
    float a0 = 0.f, a1 = 0.f, a2 = 0.f;
    for (int j = 0; j < 96; ++j) {
        float v = srow[w][j];
        a0 = __fmaf_rn(v, Wo[j*96 + c0], a0);
        a1 = __fmaf_rn(v, Wo[j*96 + c1], a1);
        a2 = __fmaf_rn(v, Wo[j*96 + c2], a2);
    }
    float y0 = __fadd_rn(x0, a0), y1 = __fadd_rn(x1v, a1), y2 = __fadd_rn(x2v, a2);
    float s = y0 + y1 + y2;
#pragma unroll
    for (int off = 16; off > 0; off >>= 1) s += __shfl_xor_sync(0xffffffffu, s, off);
    float m = s * (1.0f/96.0f);
    float d0 = y0 - m, d1 = y1 - m, d2 = y2 - m;
    float q = d0*d0 + d1*d1 + d2*d2;
#pragma unroll
    for (int off = 16; off > 0; off >>= 1) q += __shfl_xor_sync(0xffffffffu, q, off);
    float rs = rsqrtf(q*(1.0f/96.0f) + 1e-5f);
    d_x1[r*96 + c0] = __fmaf_rn(__fmul_rn(d0, rs), g1[c0], 0.f) + be1[c0];
    d_x1[r*96 + c1] = __fmaf_rn(__fmul_rn(d1, rs), g1[c1], 0.f) + be1[c1];
    d_x1[r*96 + c2] = __fmaf_rn(__fmul_rn(d2, rs), g1[c2], 0.f) + be1[c2];
}

// ---------------- 7: FFN + LN + transposed output --------------------------------
__global__ __launch_bounds__(384) void k_ffn(const float* __restrict__ W1, const float* __restrict__ b1,
                                             const float* __restrict__ W2, const float* __restrict__ b2,
                                             const float* __restrict__ g2, const float* __restrict__ be2,
                                             float* __restrict__ outF) {
    __shared__ float sx[16][96];
    __shared__ float sh[16][384];
    __shared__ float sy[16][96];
    __shared__ float sm[16], srs[16];
    const int t = threadIdx.x, r0 = blockIdx.x*16;

    for (int e = t; e < 16*96; e += 384) {
        int r = e / 96, c = e - r*96;
        sx[r][c] = d_x1[(r0 + r)*96 + c];
    }
    __syncthreads();
    { // hidden: col j = t
        int j = t;
        float acc[16];
        float bj = b1[j];
#pragma unroll
        for (int r = 0; r < 16; ++r) acc[r] = bj;
        for (int i = 0; i < 96; ++i) {
            float wv = W1[i*384 + j];
#pragma unroll
            for (int r = 0; r < 16; ++r) acc[r] = __fmaf_rn(sx[r][i], wv, acc[r]);
        }
#pragma unroll
        for (int r = 0; r < 16; ++r) sh[r][j] = fmaxf(acc[r], 0.f);
    }
    __syncthreads();
    { // output proj
        int g = t / 96, c = t - 96*g;
        float acc[4];
        float bc = b2[c];
#pragma unroll
        for (int rr = 0; rr < 4; ++rr) acc[rr] = bc;
        for (int j = 0; j < 384; ++j) {
            float wv = W2[j*96 + c];
#pragma unroll
            for (int rr = 0; rr < 4; ++rr) acc[rr] = __fmaf_rn(sh[g*4 + rr][j], wv, acc[rr]);
        }
#pragma unroll
        for (int rr = 0; rr < 4; ++rr) {
            int r = g*4 + rr;
            sy[r][c] = __fadd_rn(sx[r][c], acc[rr]);
        }
    }
    __syncthreads();
    if (t < 16) {
        float s = 0.f;
        for (int c = 0; c < 96; ++c) s += sy[t][c];
        float m = s * (1.0f/96.0f);
        float q = 0.f;
        for (int c = 0; c < 96; ++c) { float d = sy[t][c] - m; q += d*d; }
        sm[t] = m;
        srs[t] = rsqrtf(q*(1.0f/96.0f) + 1e-5f);
    }
    __syncthreads();
    {
        int g = t / 96, c = t - 96*g;
#pragma unroll
        for (int rr = 0; rr < 4; ++rr) {
            int r = g*4 + rr, row = r0 + r;
            float val = (sy[r][c] - sm[r]) * srs[r] * g2[c] + be2[c];
            int b = row >> 10, pl = row & 1023;
            outF[((long)b*96 + c)*1024 + pl] = val;
        }
    }
}

// ---------------- launch ----------------------------------------------------------
extern "C" void kernel_launch(void* const* d_in, const int* in_sizes, int n_in,
                              void* d_out, int out_size) {
    const float* pc   = (const float*)d_in[0];
    const float* col  = (const float*)d_in[1];
    const float* W_in = (const float*)d_in[2];
    const float* b_in = (const float*)d_in[3];
    const float* Wq   = (const float*)d_in[4];
    const float* Wk   = (const float*)d_in[5];
    const float* Wv   = (const float*)d_in[6];
    const float* Wo   = (const float*)d_in[7];
    const float* Wpos = (const float*)d_in[8];
    const float* W1   = (const float*)d_in[9];
    const float* b1   = (const float*)d_in[10];
    const float* W2   = (const float*)d_in[11];
    const float* b2   = (const float*)d_in[12];
    const float* g1   = (const float*)d_in[13];
    const float* be1  = (const float*)d_in[14];
    const float* g2   = (const float*)d_in[15];
    const float* be2  = (const float*)d_in[16];
    const int*   sel  = (const int*)d_in[17];
    float* out = (float*)d_out;

    k_transpose<<<(BB*NPAD + 255)/256, 256>>>(pc);
    k_fps<<<BB, 512>>>();
    k_gather<<<(NROWS + 255)/256, 256>>>(pc, col, sel, out + (long)BB*CC*NPT);
    k_neighbor<<<dim3(NPT/8, BB), 256>>>();
    k_inproj<<<NROWS/16, 96>>>(W_in, b_in, Wq, Wk, Wv);
    k_attn<<<NROWS, 192>>>(Wpos);
    k_wo_ln<<<NROWS/8, 256>>>(Wo, g1, be1);
    k_ffn<<<NROWS/16, 384>>>(W1, b1, W2, b2, g2, be2, out);
}

// round 7
// speedup vs baseline: 1.0013x; 1.0013x over previous
#include <cuda_runtime.h>

#define BB 8
#define N_IN 20000
#define NPAD 20480
#define N_ALL 1200
#define NPT 1024
#define KNB 34
#define CC 96
#define HH 6
#define NROWS (BB*NPT)

// ---------------- scratch (device globals; no allocation allowed) ----------------
__device__ float d_xs[BB*NPAD];
__device__ float d_ys[BB*NPAD];
__device__ float d_zs[BB*NPAD];
__device__ int   d_fps[BB*N_ALL];
__device__ float d_coord[NROWS*3];
__device__ float d_color[NROWS*3];
__device__ int   d_nidx[NROWS*KNB];
__device__ int   d_ncnt[NROWS];
__device__ float d_x [NROWS*CC];
__device__ float d_qb[NROWS*CC];
__device__ float d_kb[NROWS*CC];
__device__ float d_vb[NROWS*CC];
__device__ float d_ao[NROWS*CC];
__device__ float d_x1[NROWS*CC];

// ---------------- 0: SoA transpose of point clouds (pad with point 0 clone) -------
__global__ void k_transpose(const float* __restrict__ pc) {
    int idx = blockIdx.x*blockDim.x + threadIdx.x;
    if (idx >= BB*NPAD) return;
    int b = idx / NPAD, i = idx - b*NPAD;
    int src = (i < N_IN) ? i : 0;                 // pad = clone of point 0 (dist->0, never argmax)
    const float* p = pc + ((long)b*N_IN + src)*3;
    d_xs[idx] = p[0]; d_ys[idx] = p[1]; d_zs[idx] = p[2];
}

// ---------------- 1: farthest point sampling, 1 block per batch -------------------
__global__ __launch_bounds__(512, 1) void k_fps() {
    const int b = blockIdx.x, tid = threadIdx.x;
    const int lane = tid & 31, wid = tid >> 5;
    const float4* X4 = (const float4*)(d_xs + b*NPAD);
    const float4* Y4 = (const float4*)(d_ys + b*NPAD);
    const float4* Z4 = (const float4*)(d_zs + b*NPAD);
    const float* Xs = d_xs + b*NPAD;
    const float* Ys = d_ys + b*NPAD;
    const float* Zs = d_zs + b*NPAD;

    float dist[40];
#pragma unroll
    for (int i = 0; i < 40; ++i) dist[i] = 1e10f;

    __shared__ float s_v[16];
    __shared__ int   s_i[16];
    __shared__ int   s_cur;

    int cur = 0;
    for (int t = 0; t < N_ALL; ++t) {
        if (tid == 0) d_fps[b*N_ALL + t] = cur;
        float cx = __ldg(Xs + cur), cy = __ldg(Ys + cur), cz = __ldg(Zs + cur);
        float best = -1.0f; int bidx = 0;
#pragma unroll
        for (int k = 0; k < 10; ++k) {
            int f4 = k*512 + tid;                 // block-strided: warp reads contiguous 512B
            float4 px = X4[f4], py = Y4[f4], pz = Z4[f4];
#pragma unroll
            for (int m = 0; m < 4; ++m) {
                float x = (m==0)?px.x:(m==1)?px.y:(m==2)?px.z:px.w;
                float y = (m==0)?py.x:(m==1)?py.y:(m==2)?py.z:py.w;
                float z = (m==0)?pz.x:(m==1)?pz.y:(m==2)?pz.z:pz.w;
                float dx = __fadd_rn(x, -cx);
                float dy = __fadd_rn(y, -cy);
                float dz = __fadd_rn(z, -cz);
                // match XLA: mul then summed adds, no fma contraction
                float d = __fadd_rn(__fadd_rn(__fmul_rn(dx,dx), __fmul_rn(dy,dy)), __fmul_rn(dz,dz));
                int idx = k*40; // placeholder, recomputed below
                (void)idx;
                float nd = fminf(dist[k*4+m], d);
                dist[k*4+m] = nd;
                int j = f4*4 + m;
                if (nd > best) { best = nd; bidx = j; }   // strict > : first occurrence wins
            }
        }
        // warp argmax reduce (tie -> lower index)
#pragma unroll
        for (int off = 16; off > 0; off >>= 1) {
            float ov = __shfl_down_sync(0xffffffffu, best, off);
            int   oi = __shfl_down_sync(0xffffffffu, bidx, off);
            if (ov > best || (ov == best && oi < bidx)) { best = ov; bidx = oi; }
        }
        if (lane == 0) { s_v[wid] = best; s_i[wid] = bidx; }
        __syncthreads();
        if (tid == 0) {
            float bv = s_v[0]; int bi = s_i[0];
#pragma unroll
            for (int w = 1; w < 16; ++w) {
                float ov = s_v[w]; int oi = s_i[w];
                if (ov > bv || (ov == bv && oi < bi)) { bv = ov; bi = oi; }
            }
            s_cur = bi;
        }
        __syncthreads();
        cur = s_cur;
    }
}

// ---------------- 2: gather selected points (fps_idx[:, sel]) --------------------
__global__ void k_gather(const float* __restrict__ pc, const float* __restrict__ col,
                         const int* __restrict__ sel, float* __restrict__ out_coord) {
    int p = blockIdx.x*blockDim.x + threadIdx.x;
    if (p >= NROWS) return;
    int b = p >> 10, i = p & 1023;
    int gi = d_fps[b*N_ALL + sel[i]];
    const float* s  = pc  + ((long)b*N_IN + gi)*3;
    const float* s2 = col + ((long)b*N_IN + gi)*3;
    d_coord[p*3+0] = s[0];  d_coord[p*3+1] = s[1];  d_coord[p*3+2] = s[2];
    d_color[p*3+0] = s2[0]; d_color[p*3+1] = s2[1]; d_color[p*3+2] = s2[2];
    out_coord[p*3+0] = s[0]; out_coord[p*3+1] = s[1]; out_coord[p*3+2] = s[2];
}

// ---------------- 3: radius neighbors, one warp per query point ------------------
__global__ __launch_bounds__(256) void k_neighbor() {
    __shared__ float sx[NPT], sy[NPT], sz[NPT];
    const int b = blockIdx.y;
    for (int i = threadIdx.x; i < NPT; i += 256) {
        const float* cp = d_coord + (b*NPT + i)*3;
        sx[i] = cp[0]; sy[i] = cp[1]; sz[i] = cp[2];
    }
    __syncthreads();
    const int warp = threadIdx.x >> 5, lane = threadIdx.x & 31;
    const int pl = blockIdx.x*8 + warp;
    const int p  = b*NPT + pl;
    const float qx = sx[pl], qy = sy[pl], qz = sz[pl];
    const float R2 = 0.010000000000000002f;
    float key[32];
    int nv = 0;
#pragma unroll
    for (int i = 0; i < 32; ++i) {
        int c = i*32 + lane;
        float dx = __fadd_rn(qx, -sx[c]);
        float dy = __fadd_rn(qy, -sy[c]);
        float dz = __fadd_rn(qz, -sz[c]);
        float d2 = __fadd_rn(__fadd_rn(__fmul_rn(dx,dx), __fmul_rn(dy,dy)), __fmul_rn(dz,dz));
        bool v = (d2 <= R2);
        key[i] = v ? d2 : 1e10f;
        nv += v ? 1 : 0;
    }
    int total = nv;
#pragma unroll
    for (int off = 16; off > 0; off >>= 1) total += __shfl_xor_sync(0xffffffffu, total, off);

    int* my = d_nidx + p*KNB;
    if (total <= KNB) {
        int pos = 0;
#pragma unroll
        for (int i = 0; i < 32; ++i) {
            bool v = key[i] < 1e9f;
            unsigned m = __ballot_sync(0xffffffffu, v);
            if (v) my[pos + __popc(m & ((1u<<lane)-1u))] = i*32 + lane;
            pos += __popc(m);
        }
        for (int s = pos + lane; s < KNB; s += 32) my[s] = pl;  // padded slots: self
        if (lane == 0) d_ncnt[p] = total;
    } else {
        for (int s = 0; s < KNB; ++s) {
            float bv = 3e10f; int bi = 0x7fffffff;
#pragma unroll
            for (int i = 0; i < 32; ++i) {
                int c = i*32 + lane;
                if (key[i] < bv || (key[i] == bv && c < bi)) { bv = key[i]; bi = c; }
            }
#pragma unroll
            for (int off = 16; off > 0; off >>= 1) {
                float ov = __shfl_xor_sync(0xffffffffu, bv, off);
                int   oi = __shfl_xor_sync(0xffffffffu, bi, off);
                if (ov < bv || (ov == bv && oi < bi)) { bv = ov; bi = oi; }
            }
            if ((bi & 31) == lane) {
#pragma unroll
                for (int i = 0; i < 32; ++i) if (i*32 + lane == bi) key[i] = 2e10f;
            }
            if (lane == 0) my[s] = bi;
        }
        if (lane == 0) d_ncnt[p] = KNB;
    }
}

// ---------------- 4: x = feat@W_in+b ; q,k,v projections -------------------------
__global__ __launch_bounds__(96) void k_inproj(const float* __restrict__ Wi, const float* __restrict__ bi,
                                               const float* __restrict__ Wq, const float* __restrict__ Wk,
                                               const float* __restrict__ Wv) {
    __shared__ float sf[16][6];
    __shared__ float sx[16][96];
    const int t = threadIdx.x, r0 = blockIdx.x*16;
    {
        int r = t/6, j = t - r*6, row = r0 + r;
        sf[r][j] = (j < 3) ? d_color[row*3 + j] : d_coord[row*3 + j - 3];
    }
    __syncthreads();
    const int c = t;
    const float bc = bi[c];
#pragma unroll
    for (int r = 0; r < 16; ++r) {
        float a = bc;
#pragma unroll
        for (int j = 0; j < 6; ++j) a = __fmaf_rn(sf[r][j], Wi[j*96 + c], a);
        sx[r][c] = a;
        d_x[(r0 + r)*96 + c] = a;
    }
    __syncthreads();
    float aq[16], ak[16], av[16];
#pragma unroll
    for (int r = 0; r < 16; ++r) { aq[r] = 0.f; ak[r] = 0.f; av[r] = 0.f; }
    for (int j = 0; j < 96; ++j) {
        float wq = Wq[j*96 + c], wk = Wk[j*96 + c], wv = Wv[j*96 + c];
#pragma unroll
        for (int r = 0; r < 16; ++r) {
            float xv = sx[r][j];
            aq[r] = __fmaf_rn(xv, wq, aq[r]);
            ak[r] = __fmaf_rn(xv, wk, ak[r]);
            av[r] = __fmaf_rn(xv, wv, av[r]);
        }
    }
#pragma unroll
    for (int r = 0; r < 16; ++r) {
        d_qb[(r0 + r)*96 + c] = aq[r];
        d_kb[(r0 + r)*96 + c] = ak[r];
        d_vb[(r0 + r)*96 + c] = av[r];
    }
}

// ---------------- 5: local attention, one block per point ------------------------
__global__ __launch_bounds__(192) void k_attn(const float* __restrict__ Wpos) {
    const int p = blockIdx.x, pl = p & 1023, base = p - pl;
    const int t = threadIdx.x;
    __shared__ float sq[96];
    __shared__ float skn[KNB][96];
    __shared__ float svn[KNB][96];
    __shared__ float sdx[KNB], sdy[KNB], sdz[KNB];
    __shared__ int   snb[KNB];
    __shared__ float slog[HH*KNB];
    __shared__ int   scnt;

    if (t < KNB) {
        int nb = d_nidx[p*KNB + t];
        snb[t] = nb;
        int gn = base + nb;
        sdx[t] = __fadd_rn(d_coord[p*3+0], -d_coord[gn*3+0]);
        sdy[t] = __fadd_rn(d_coord[p*3+1], -d_coord[gn*3+1]);
        sdz[t] = __fadd_rn(d_coord[p*3+2], -d_coord[gn*3+2]);
    }
    if (t < 96) sq[t] = d_qb[p*96 + t];
    if (t == 0) scnt = d_ncnt[p];
    __syncthreads();

    for (int e = t; e < KNB*96; e += 192) {
        int kk = e / 96, c = e - kk*96;
        int gn = base + snb[kk];
        float pe = __fmaf_rn(sdz[kk], Wpos[192 + c],
                   __fmaf_rn(sdy[kk], Wpos[96 + c],
                   __fmul_rn(sdx[kk], Wpos[c])));
        skn[kk][c] = __fadd_rn(d_kb[gn*96 + c], pe);
        svn[kk][c] = __fadd_rn(d_vb[gn*96 + c], pe);
    }
    __syncthreads();

    const int cnt = scnt;
    for (int e = t; e < HH*KNB; e += 192) {
        int h = e / KNB, kk = e - h*KNB;
        float a = 0.f;
#pragma unroll
        for (int d = 0; d < 16; ++d) a = __fmaf_rn(sq[h*16 + d], skn[kk][h*16 + d], a);
        slog[h*KNB + kk] = (kk < cnt) ? __fmul_rn(a, 0.25f) : -1e9f;
    }
    __syncthreads();

    { // softmax: warp w == head w (6 warps exactly)
        int w = t >> 5, lane = t & 31;
        float v0 = slog[w*KNB + lane];
        float v1 = (lane < 2) ? slog[w*KNB + 32 + lane] : -3.0e38f;
        float m = fmaxf(v0, v1);
#pragma unroll
        for (int off = 16; off > 0; off >>= 1) m = fmaxf(m, __shfl_xor_sync(0xffffffffu, m, off));
        float e0 = expf(v0 - m);
        float e1 = (lane < 2) ? expf(v1 - m) : 0.f;
        float s = e0 + e1;
#pragma unroll
        for (int off = 16; off > 0; off >>= 1) s += __shfl_xor_sync(0xffffffffu, s, off);
        float inv = 1.0f / s;
        slog[w*KNB + lane] = e0 * inv;
        if (lane < 2) slog[w*KNB + 32 + lane] = e1 * inv;
    }
    __syncthreads();

    if (t < 96) {
        int h = t >> 4;
        float a = 0.f;
#pragma unroll
        for (int kk = 0; kk < KNB; ++kk) a = __fmaf_rn(slog[h*KNB + kk], svn[kk][t], a);
        d_ao[p*96 + t] = a;
    }
}

// ---------------- 6: x1 = LN(x + ao@Wo), one warp per row ------------------------
__global__ __launch_bounds__(256) void k_wo_ln(const float* __restrict__ Wo, const float* __restrict__ g1,
                                               const float* __restrict__ be1) {
    __shared__ float srow[8][96];
    const int w = threadIdx.x >> 5, lane = threadIdx.x & 31;
    const int r = blockIdx.x*8 + w;
    const int c0 = lane, c1 = lane + 32, c2 = lane + 64;
    srow[w][c0] = d_ao[r*96 + c0];
    srow[w][c1] = d_ao[r*96 + c1];
    srow[w][c2] = d_ao[r*96 + c2];
    float x0 = d_x[r*96 + c0], x1v = d_x[r*96 + c1], x2v = d_x[r*96 + c2];
    __syncwarp();
    float a0 = 0.f, a1 = 0.f, a2 = 0.f;
    for (int j = 0; j < 96; ++j) {
        float v = srow[w][j];
        a0 = __fmaf_rn(v, Wo[j*96 + c0], a0);
        a1 = __fmaf_rn(v, Wo[j*96 + c1], a1);
        a2 = __fmaf_rn(v, Wo[j*96 + c2], a2);
    }
    float y0 = __fadd_rn(x0, a0), y1 = __fadd_rn(x1v, a1), y2 = __fadd_rn(x2v, a2);
    float s = y0 + y1 + y2;
#pragma unroll
    for (int off = 16; off > 0; off >>= 1) s += __shfl_xor_sync(0xffffffffu, s, off);
    float m = s * (1.0f/96.0f);
    float d0 = y0 - m, d1 = y1 - m, d2 = y2 - m;
    float q = d0*d0 + d1*d1 + d2*d2;
#pragma unroll
    for (int off = 16; off > 0; off >>= 1) q += __shfl_xor_sync(0xffffffffu, q, off);
    float rs = rsqrtf(q*(1.0f/96.0f) + 1e-5f);
    d_x1[r*96 + c0] = __fmaf_rn(__fmul_rn(d0, rs), g1[c0], 0.f) + be1[c0];
    d_x1[r*96 + c1] = __fmaf_rn(__fmul_rn(d1, rs), g1[c1], 0.f) + be1[c1];
    d_x1[r*96 + c2] = __fmaf_rn(__fmul_rn(d2, rs), g1[c2], 0.f) + be1[c2];
}

// ---------------- 7: FFN + LN + transposed output --------------------------------
__global__ __launch_bounds__(384) void k_ffn(const float* __restrict__ W1, const float* __restrict__ b1,
                                             const float* __restrict__ W2, const float* __restrict__ b2,
                                             const float* __restrict__ g2, const float* __restrict__ be2,
                                             float* __restrict__ outF) {
    __shared__ float sx[16][96];
    __shared__ float sh[16][384];
    __shared__ float sy[16][96];
    __shared__ float sm[16], srs[16];
    const int t = threadIdx.x, r0 = blockIdx.x*16;

    for (int e = t; e < 16*96; e += 384) {
        int r = e / 96, c = e - r*96;
        sx[r][c] = d_x1[(r0 + r)*96 + c];
    }
    __syncthreads();
    { // hidden: col j = t
        int j = t;
        float acc[16];
        float bj = b1[j];
#pragma unroll
        for (int r = 0; r < 16; ++r) acc[r] = bj;
        for (int i = 0; i < 96; ++i) {
            float wv = W1[i*384 + j];
#pragma unroll
            for (int r = 0; r < 16; ++r) acc[r] = __fmaf_rn(sx[r][i], wv, acc[r]);
        }
#pragma unroll
        for (int r = 0; r < 16; ++r) sh[r][j] = fmaxf(acc[r], 0.f);
    }
    __syncthreads();
    { // output proj
        int g = t / 96, c = t - 96*g;
        float acc[4];
        float bc = b2[c];
#pragma unroll
        for (int rr = 0; rr < 4; ++rr) acc[rr] = bc;
        for (int j = 0; j < 384; ++j) {
            float wv = W2[j*96 + c];
#pragma unroll
            for (int rr = 0; rr < 4; ++rr) acc[rr] = __fmaf_rn(sh[g*4 + rr][j], wv, acc[rr]);
        }
#pragma unroll
        for (int rr = 0; rr < 4; ++rr) {
            int r = g*4 + rr;
            sy[r][c] = __fadd_rn(sx[r][c], acc[rr]);
        }
    }
    __syncthreads();
    if (t < 16) {
        float s = 0.f;
        for (int c = 0; c < 96; ++c) s += sy[t][c];
        float m = s * (1.0f/96.0f);
        float q = 0.f;
        for (int c = 0; c < 96; ++c) { float d = sy[t][c] - m; q += d*d; }
        sm[t] = m;
        srs[t] = rsqrtf(q*(1.0f/96.0f) + 1e-5f);
    }
    __syncthreads();
    {
        int g = t / 96, c = t - 96*g;
#pragma unroll
        for (int rr = 0; rr < 4; ++rr) {
            int r = g*4 + rr, row = r0 + r;
            float val = (sy[r][c] - sm[r]) * srs[r] * g2[c] + be2[c];
            int b = row >> 10, pl = row & 1023;
            outF[((long)b*96 + c)*1024 + pl] = val;
        }
    }
}

// ---------------- launch ----------------------------------------------------------
extern "C" void kernel_launch(void* const* d_in, const int* in_sizes, int n_in,
                              void* d_out, int out_size) {
    const float* pc   = (const float*)d_in[0];
    const float* col  = (const float*)d_in[1];
    const float* W_in = (const float*)d_in[2];
    const float* b_in = (const float*)d_in[3];
    const float* Wq   = (const float*)d_in[4];
    const float* Wk   = (const float*)d_in[5];
    const float* Wv   = (const float*)d_in[6];
    const float* Wo   = (const float*)d_in[7];
    const float* Wpos = (const float*)d_in[8];
    const float* W1   = (const float*)d_in[9];
    const float* b1   = (const float*)d_in[10];
    const float* W2   = (const float*)d_in[11];
    const float* b2   = (const float*)d_in[12];
    const float* g1   = (const float*)d_in[13];
    const float* be1  = (const float*)d_in[14];
    const float* g2   = (const float*)d_in[15];
    const float* be2  = (const float*)d_in[16];
    const int*   sel  = (const int*)d_in[17];
    float* out = (float*)d_out;

    k_transpose<<<(BB*NPAD + 255)/256, 256>>>(pc);
    k_fps<<<BB, 512>>>();
    k_gather<<<(NROWS + 255)/256, 256>>>(pc, col, sel, out + (long)BB*CC*NPT);
    k_neighbor<<<dim3(NPT/8, BB), 256>>>();
    k_inproj<<<NROWS/16, 96>>>(W_in, b_in, Wq, Wk, Wv);
    k_attn<<<NROWS, 192>>>(Wpos);
    k_wo_ln<<<NROWS/8, 256>>>(Wo, g1, be1);
    k_ffn<<<NROWS/16, 384>>>(W1, b1, W2, b2, g2, be2, out);
}

// round 9
// speedup vs baseline: 1.0019x; 1.0006x over previous
#include <cuda_runtime.h>

#define BB 8
#define N_IN 20000
#define NPAD 20480
#define N_ALL 1200
#define NPT 1024
#define KNB 34
#define CC 96
#define HH 6
#define NROWS (BB*NPT)

// ---------------- scratch (device globals; no allocation allowed) ----------------
__device__ float d_xs[BB*NPAD];
__device__ float d_ys[BB*NPAD];
__device__ float d_zs[BB*NPAD];
__device__ int   d_fps[BB*N_ALL];
__device__ float d_coord[NROWS*3];
__device__ float d_color[NROWS*3];
__device__ int   d_nidx[NROWS*KNB];
__device__ int   d_ncnt[NROWS];
__device__ float d_x [NROWS*CC];
__device__ float d_qb[NROWS*CC];
__device__ float d_kb[NROWS*CC];
__device__ float d_vb[NROWS*CC];
__device__ float d_ao[NROWS*CC];
__device__ float d_x1[NROWS*CC];

// ---------------- 0: SoA transpose of point clouds (pad with point 0 clone) -------
__global__ void k_transpose(const float* __restrict__ pc) {
    int idx = blockIdx.x*blockDim.x + threadIdx.x;
    if (idx >= BB*NPAD) return;
    int b = idx / NPAD, i = idx - b*NPAD;
    int src = (i < N_IN) ? i : 0;                 // pad = clone of point 0 (dist->0, never argmax)
    const float* p = pc + ((long)b*N_IN + src)*3;
    d_xs[idx] = p[0]; d_ys[idx] = p[1]; d_zs[idx] = p[2];
}

// ---------------- 1: farthest point sampling, 1 block per batch -------------------
__global__ __launch_bounds__(512, 1) void k_fps() {
    const int b = blockIdx.x, tid = threadIdx.x;
    const int lane = tid & 31, wid = tid >> 5;
    const float4* X4 = (const float4*)(d_xs + b*NPAD);
    const float4* Y4 = (const float4*)(d_ys + b*NPAD);
    const float4* Z4 = (const float4*)(d_zs + b*NPAD);
    const float* Xs = d_xs + b*NPAD;
    const float* Ys = d_ys + b*NPAD;
    const float* Zs = d_zs + b*NPAD;

    float dist[40];
#pragma unroll
    for (int i = 0; i < 40; ++i) dist[i] = 1e10f;

    __shared__ float s_v[16];
    __shared__ int   s_i[16];
    __shared__ int   s_cur;

    int cur = 0;
    for (int t = 0; t < N_ALL; ++t) {
        if (tid == 0) d_fps[b*N_ALL + t] = cur;
        float cx = __ldg(Xs + cur), cy = __ldg(Ys + cur), cz = __ldg(Zs + cur);
        float best = -1.0f; int bidx = 0;
#pragma unroll
        for (int k = 0; k < 10; ++k) {
            int f4 = k*512 + tid;                 // block-strided: warp reads contiguous 512B
            float4 px = X4[f4], py = Y4[f4], pz = Z4[f4];
#pragma unroll
            for (int m = 0; m < 4; ++m) {
                float x = (m==0)?px.x:(m==1)?px.y:(m==2)?px.z:px.w;
                float y = (m==0)?py.x:(m==1)?py.y:(m==2)?py.z:py.w;
                float z = (m==0)?pz.x:(m==1)?pz.y:(m==2)?pz.z:pz.w;
                float dx = __fadd_rn(x, -cx);
                float dy = __fadd_rn(y, -cy);
                float dz = __fadd_rn(z, -cz);
                // match XLA: mul then summed adds, no fma contraction
                float d = __fadd_rn(__fadd_rn(__fmul_rn(dx,dx), __fmul_rn(dy,dy)), __fmul_rn(dz,dz));
                int idx = k*40; // placeholder, recomputed below
                (void)idx;
                float nd = fminf(dist[k*4+m], d);
                dist[k*4+m] = nd;
                int j = f4*4 + m;
                if (nd > best) { best = nd; bidx = j; }   // strict > : first occurrence wins
            }
        }
        // warp argmax reduce (tie -> lower index)
#pragma unroll
        for (int off = 16; off > 0; off >>= 1) {
            float ov = __shfl_down_sync(0xffffffffu, best, off);
            int   oi = __shfl_down_sync(0xffffffffu, bidx, off);
            if (ov > best || (ov == best && oi < bidx)) { best = ov; bidx = oi; }
        }
        if (lane == 0) { s_v[wid] = best; s_i[wid] = bidx; }
        __syncthreads();
        if (tid == 0) {
            float bv = s_v[0]; int bi = s_i[0];
#pragma unroll
            for (int w = 1; w < 16; ++w) {
                float ov = s_v[w]; int oi = s_i[w];
                if (ov > bv || (ov == bv && oi < bi)) { bv = ov; bi = oi; }
            }
            s_cur = bi;
        }
        __syncthreads();
        cur = s_cur;
    }
}

// ---------------- 2: gather selected points (fps_idx[:, sel]) --------------------
__global__ void k_gather(const float* __restrict__ pc, const float* __restrict__ col,
                         const int* __restrict__ sel, float* __restrict__ out_coord) {
    int p = blockIdx.x*blockDim.x + threadIdx.x;
    if (p >= NROWS) return;
    int b = p >> 10, i = p & 1023;
    int gi = d_fps[b*N_ALL + sel[i]];
    const float* s  = pc  + ((long)b*N_IN + gi)*3;
    const float* s2 = col + ((long)b*N_IN + gi)*3;
    d_coord[p*3+0] = s[0];  d_coord[p*3+1] = s[1];  d_coord[p*3+2] = s[2];
    d_color[p*3+0] = s2[0]; d_color[p*3+1] = s2[1]; d_color[p*3+2] = s2[2];
    out_coord[p*3+0] = s[0]; out_coord[p*3+1] = s[1]; out_coord[p*3+2] = s[2];
}

// ---------------- 3: radius neighbors, one warp per query point ------------------
__global__ __launch_bounds__(256) void k_neighbor() {
    __shared__ float sx[NPT], sy[NPT], sz[NPT];
    const int b = blockIdx.y;
    for (int i = threadIdx.x; i < NPT; i += 256) {
        const float* cp = d_coord + (b*NPT + i)*3;
        sx[i] = cp[0]; sy[i] = cp[1]; sz[i] = cp[2];
    }
    __syncthreads();
    const int warp = threadIdx.x >> 5, lane = threadIdx.x & 31;
    const int pl = blockIdx.x*8 + warp;
    const int p  = b*NPT + pl;
    const float qx = sx[pl], qy = sy[pl], qz = sz[pl];
    const float R2 = 0.010000000000000002f;
    float key[32];
    int nv = 0;
#pragma unroll
    for (int i = 0; i < 32; ++i) {
        int c = i*32 + lane;
        float dx = __fadd_rn(qx, -sx[c]);
        float dy = __fadd_rn(qy, -sy[c]);
        float dz = __fadd_rn(qz, -sz[c]);
        float d2 = __fadd_rn(__fadd_rn(__fmul_rn(dx,dx), __fmul_rn(dy,dy)), __fmul_rn(dz,dz));
        bool v = (d2 <= R2);
        key[i] = v ? d2 : 1e10f;
        nv += v ? 1 : 0;
    }
    int total = nv;
#pragma unroll
    for (int off = 16; off > 0; off >>= 1) total += __shfl_xor_sync(0xffffffffu, total, off);

    int* my = d_nidx + p*KNB;
    if (total <= KNB) {
        int pos = 0;
#pragma unroll
        for (int i = 0; i < 32; ++i) {
            bool v = key[i] < 1e9f;
            unsigned m = __ballot_sync(0xffffffffu, v);
            if (v) my[pos + __popc(m & ((1u<<lane)-1u))] = i*32 + lane;
            pos += __popc(m);
        }
        for (int s = pos + lane; s < KNB; s += 32) my[s] = pl;  // padded slots: self
        if (lane == 0) d_ncnt[p] = total;
    } else {
        for (int s = 0; s < KNB; ++s) {
            float bv = 3e10f; int bi = 0x7fffffff;
#pragma unroll
            for (int i = 0; i < 32; ++i) {
                int c = i*32 + lane;
                if (key[i] < bv || (key[i] == bv && c < bi)) { bv = key[i]; bi = c; }
            }
#pragma unroll
            for (int off = 16; off > 0; off >>= 1) {
                float ov = __shfl_xor_sync(0xffffffffu, bv, off);
                int   oi = __shfl_xor_sync(0xffffffffu, bi, off);
                if (ov < bv || (ov == bv && oi < bi)) { bv = ov; bi = oi; }
            }
            if ((bi & 31) == lane) {
#pragma unroll
                for (int i = 0; i < 32; ++i) if (i*32 + lane == bi) key[i] = 2e10f;
            }
            if (lane == 0) my[s] = bi;
        }
        if (lane == 0) d_ncnt[p] = KNB;
    }
}

// ---------------- 4: x = feat@W_in+b ; q,k,v projections -------------------------
__global__ __launch_bounds__(96) void k_inproj(const float* __restrict__ Wi, const float* __restrict__ bi,
                                               const float* __restrict__ Wq, const float* __restrict__ Wk,
                                               const float* __restrict__ Wv) {
    __shared__ float sf[16][6];
    __shared__ float sx[16][96];
    const int t = threadIdx.x, r0 = blockIdx.x*16;
    {
        int r = t/6, j = t - r*6, row = r0 + r;
        sf[r][j] = (j < 3) ? d_color[row*3 + j] : d_coord[row*3 + j - 3];
    }
    __syncthreads();
    const int c = t;
    const float bc = bi[c];
#pragma unroll
    for (int r = 0; r < 16; ++r) {
        float a = bc;
#pragma unroll
        for (int j = 0; j < 6; ++j) a = __fmaf_rn(sf[r][j], Wi[j*96 + c], a);
        sx[r][c] = a;
        d_x[(r0 + r)*96 + c] = a;
    }
    __syncthreads();
    float aq[16], ak[16], av[16];
#pragma unroll
    for (int r = 0; r < 16; ++r) { aq[r] = 0.f; ak[r] = 0.f; av[r] = 0.f; }
    for (int j = 0; j < 96; ++j) {
        float wq = Wq[j*96 + c], wk = Wk[j*96 + c], wv = Wv[j*96 + c];
#pragma unroll
        for (int r = 0; r < 16; ++r) {
            float xv = sx[r][j];
            aq[r] = __fmaf_rn(xv, wq, aq[r]);
            ak[r] = __fmaf_rn(xv, wk, ak[r]);
            av[r] = __fmaf_rn(xv, wv, av[r]);
        }
    }
#pragma unroll
    for (int r = 0; r < 16; ++r) {
        d_qb[(r0 + r)*96 + c] = aq[r];
        d_kb[(r0 + r)*96 + c] = ak[r];
        d_vb[(r0 + r)*96 + c] = av[r];
    }
}

// ---------------- 5: local attention, one block per point ------------------------
__global__ __launch_bounds__(192) void k_attn(const float* __restrict__ Wpos) {
    const int p = blockIdx.x, pl = p & 1023, base = p - pl;
    const int t = threadIdx.x;
    __shared__ float sq[96];
    __shared__ float skn[KNB][96];
    __shared__ float svn[KNB][96];
    __shared__ float sdx[KNB], sdy[KNB], sdz[KNB];
    __shared__ int   snb[KNB];
    __shared__ float slog[HH*KNB];
    __shared__ int   scnt;

    if (t < KNB) {
        int nb = d_nidx[p*KNB + t];
        snb[t] = nb;
        int gn = base + nb;
        sdx[t] = __fadd_rn(d_coord[p*3+0], -d_coord[gn*3+0]);
        sdy[t] = __fadd_rn(d_coord[p*3+1], -d_coord[gn*3+1]);
        sdz[t] = __fadd_rn(d_coord[p*3+2], -d_coord[gn*3+2]);
    }
    if (t < 96) sq[t] = d_qb[p*96 + t];
    if (t == 0) scnt = d_ncnt[p];
    __syncthreads();

    for (int e = t; e < KNB*96; e += 192) {
        int kk = e / 96, c = e - kk*96;
        int gn = base + snb[kk];
        float pe = __fmaf_rn(sdz[kk], Wpos[192 + c],
                   __fmaf_rn(sdy[kk], Wpos[96 + c],
                   __fmul_rn(sdx[kk], Wpos[c])));
        skn[kk][c] = __fadd_rn(d_kb[gn*96 + c], pe);
        svn[kk][c] = __fadd_rn(d_vb[gn*96 + c], pe);
    }
    __syncthreads();

    const int cnt = scnt;
    for (int e = t; e < HH*KNB; e += 192) {
        int h = e / KNB, kk = e - h*KNB;
        float a = 0.f;
#pragma unroll
        for (int d = 0; d < 16; ++d) a = __fmaf_rn(sq[h*16 + d], skn[kk][h*16 + d], a);
        slog[h*KNB + kk] = (kk < cnt) ? __fmul_rn(a, 0.25f) : -1e9f;
    }
    __syncthreads();

    { // softmax: warp w == head w (6 warps exactly)
        int w = t >> 5, lane = t & 31;
        float v0 = slog[w*KNB + lane];
        float v1 = (lane < 2) ? slog[w*KNB + 32 + lane] : -3.0e38f;
        float m = fmaxf(v0, v1);
#pragma unroll
        for (int off = 16; off > 0; off >>= 1) m = fmaxf(m, __shfl_xor_sync(0xffffffffu, m, off));
        float e0 = expf(v0 - m);
        float e1 = (lane < 2) ? expf(v1 - m) : 0.f;
        float s = e0 + e1;
#pragma unroll
        for (int off = 16; off > 0; off >>= 1) s += __shfl_xor_sync(0xffffffffu, s, off);
        float inv = 1.0f / s;
        slog[w*KNB + lane] = e0 * inv;
        if (lane < 2) slog[w*KNB + 32 + lane] = e1 * inv;
    }
    __syncthreads();

    if (t < 96) {
        int h = t >> 4;
        float a = 0.f;
#pragma unroll
        for (int kk = 0; kk < KNB; ++kk) a = __fmaf_rn(slog[h*KNB + kk], svn[kk][t], a);
        d_ao[p*96 + t] = a;
    }
}

// ---------------- 6: x1 = LN(x + ao@Wo), one warp per row ------------------------
__global__ __launch_bounds__(256) void k_wo_ln(const float* __restrict__ Wo, const float* __restrict__ g1,
                                               const float* __restrict__ be1) {
    __shared__ float srow[8][96];
    const int w = threadIdx.x >> 5, lane = threadIdx.x & 31;
    const int r = blockIdx.x*8 + w;
    const int c0 = lane, c1 = lane + 32, c2 = lane + 64;
    srow[w][c0] = d_ao[r*96 + c0];
    srow[w][c1] = d_ao[r*96 + c1];
    srow[w][c2] = d_ao[r*96 + c2];
    float x0 = d_x[r*96 + c0], x1v = d_x[r*96 + c1], x2v = d_x[r*96 + c2];
    __syncwarp();
    float a0 = 0.f, a1 = 0.f, a2 = 0.f;
    for (int j = 0; j < 96; ++j) {
        float v = srow[w][j];
        a0 = __fmaf_rn(v, Wo[j*96 + c0], a0);
        a1 = __fmaf_rn(v, Wo[j*96 + c1], a1);
        a2 = __fmaf_rn(v, Wo[j*96 + c2], a2);
    }
    float y0 = __fadd_rn(x0, a0), y1 = __fadd_rn(x1v, a1), y2 = __fadd_rn(x2v, a2);
    float s = y0 + y1 + y2;
#pragma unroll
    for (int off = 16; off > 0; off >>= 1) s += __shfl_xor_sync(0xffffffffu, s, off);
    float m = s * (1.0f/96.0f);
    float d0 = y0 - m, d1 = y1 - m, d2 = y2 - m;
    float q = d0*d0 + d1*d1 + d2*d2;
#pragma unroll
    for (int off = 16; off > 0; off >>= 1) q += __shfl_xor_sync(0xffffffffu, q, off);
    float rs = rsqrtf(q*(1.0f/96.0f) + 1e-5f);
    d_x1[r*96 + c0] = __fmaf_rn(__fmul_rn(d0, rs), g1[c0], 0.f) + be1[c0];
    d_x1[r*96 + c1] = __fmaf_rn(__fmul_rn(d1, rs), g1[c1], 0.f) + be1[c1];
    d_x1[r*96 + c2] = __fmaf_rn(__fmul_rn(d2, rs), g1[c2], 0.f) + be1[c2];
}

// ---------------- 7: FFN + LN + transposed output --------------------------------
__global__ __launch_bounds__(384) void k_ffn(const float* __restrict__ W1, const float* __restrict__ b1,
                                             const float* __restrict__ W2, const float* __restrict__ b2,
                                             const float* __restrict__ g2, const float* __restrict__ be2,
                                             float* __restrict__ outF) {
    __shared__ float sx[16][96];
    __shared__ float sh[16][384];
    __shared__ float sy[16][96];
    __shared__ float sm[16], srs[16];
    const int t = threadIdx.x, r0 = blockIdx.x*16;

    for (int e = t; e < 16*96; e += 384) {
        int r = e / 96, c = e - r*96;
        sx[r][c] = d_x1[(r0 + r)*96 + c];
    }
    __syncthreads();
    { // hidden: col j = t
        int j = t;
        float acc[16];
        float bj = b1[j];
#pragma unroll
        for (int r = 0; r < 16; ++r) acc[r] = bj;
        for (int i = 0; i < 96; ++i) {
            float wv = W1[i*384 + j];
#pragma unroll
            for (int r = 0; r < 16; ++r) acc[r] = __fmaf_rn(sx[r][i], wv, acc[r]);
        }
#pragma unroll
        for (int r = 0; r < 16; ++r) sh[r][j] = fmaxf(acc[r], 0.f);
    }
    __syncthreads();
    { // output proj
        int g = t / 96, c = t - 96*g;
        float acc[4];
        float bc = b2[c];
#pragma unroll
        for (int rr = 0; rr < 4; ++rr) acc[rr] = bc;
        for (int j = 0; j < 384; ++j) {
            float wv = W2[j*96 + c];
#pragma unroll
            for (int rr = 0; rr < 4; ++rr) acc[rr] = __fmaf_rn(sh[g*4 + rr][j], wv, acc[rr]);
        }
#pragma unroll
        for (int rr = 0; rr < 4; ++rr) {
            int r = g*4 + rr;
            sy[r][c] = __fadd_rn(sx[r][c], acc[rr]);
        }
    }
    __syncthreads();
    if (t < 16) {
        float s = 0.f;
        for (int c = 0; c < 96; ++c) s += sy[t][c];
        float m = s * (1.0f/96.0f);
        float q = 0.f;
        for (int c = 0; c < 96; ++c) { float d = sy[t][c] - m; q += d*d; }
        sm[t] = m;
        srs[t] = rsqrtf(q*(1.0f/96.0f) + 1e-5f);
    }
    __syncthreads();
    {
        int g = t / 96, c = t - 96*g;
#pragma unroll
        for (int rr = 0; rr < 4; ++rr) {
            int r = g*4 + rr, row = r0 + r;
            float val = (sy[r][c] - sm[r]) * srs[r] * g2[c] + be2[c];
            int b = row >> 10, pl = row & 1023;
            outF[((long)b*96 + c)*1024 + pl] = val;
        }
    }
}

// ---------------- launch ----------------------------------------------------------
extern "C" void kernel_launch(void* const* d_in, const int* in_sizes, int n_in,
                              void* d_out, int out_size) {
    const float* pc   = (const float*)d_in[0];
    const float* col  = (const float*)d_in[1];
    const float* W_in = (const float*)d_in[2];
    const float* b_in = (const float*)d_in[3];
    const float* Wq   = (const float*)d_in[4];
    const float* Wk   = (const float*)d_in[5];
    const float* Wv   = (const float*)d_in[6];
    const float* Wo   = (const float*)d_in[7];
    const float* Wpos = (const float*)d_in[8];
    const float* W1   = (const float*)d_in[9];
    const float* b1   = (const float*)d_in[10];
    const float* W2   = (const float*)d_in[11];
    const float* b2   = (const float*)d_in[12];
    const float* g1   = (const float*)d_in[13];
    const float* be1  = (const float*)d_in[14];
    const float* g2   = (const float*)d_in[15];
    const float* be2  = (const float*)d_in[16];
    const int*   sel  = (const int*)d_in[17];
    float* out = (float*)d_out;

    k_transpose<<<(BB*NPAD + 255)/256, 256>>>(pc);
    k_fps<<<BB, 512>>>();
    k_gather<<<(NROWS + 255)/256, 256>>>(pc, col, sel, out + (long)BB*CC*NPT);
    k_neighbor<<<dim3(NPT/8, BB), 256>>>();
    k_inproj<<<NROWS/16, 96>>>(W_in, b_in, Wq, Wk, Wv);
    k_attn<<<NROWS, 192>>>(Wpos);
    k_wo_ln<<<NROWS/8, 256>>>(Wo, g1, be1);
    k_ffn<<<NROWS/16, 384>>>(W1, b1, W2, b2, g2, be2, out);
}